// round 12
// baseline (speedup 1.0000x reference)
#include <cuda_runtime.h>
#include <cuda_fp16.h>

// ---------------- problem constants ----------------
#define Fdim   8
#define Tdim   5
#define Zdim   16
#define Ydim   96
#define Xdim   96
#define NRAYS  32768
#define KSAMP  128
#define CIN    128               // Fdim*Zdim
#define VOXT   (Zdim*Ydim*Xdim)  // 147456 per t
#define VOXALL (Tdim*VOXT)       // 737280

// ---------------- scratch (device globals; no allocation) ----------------
__device__ float g_W2[CIN * 27 * Zdim];   // folded weights [ci][k][zo]
__device__ float g_bias2[Zdim];
__device__ float g_Spart[8][VOXALL];      // per-ci-chunk partial conv outputs
__device__ float g_S[VOXALL];             // combined density pre-activation volume
__device__ uint4 g_S8[VOXALL];            // 8 fp16 trilinear corners per cell
__device__ float g_lo[Tdim], g_hi[Tdim];  // global per-t clip bounds

// ---------------- f32x2 helpers ----------------
__device__ __forceinline__ unsigned long long pack2(float x) {
    unsigned long long r;
    unsigned u = __float_as_uint(x);
    asm("mov.b64 %0, {%1, %1};" : "=l"(r) : "r"(u));
    return r;
}
__device__ __forceinline__ void fma2(unsigned long long& c, unsigned long long a,
                                     unsigned long long b) {
    asm("fma.rn.f32x2 %0, %1, %2, %0;" : "+l"(c) : "l"(a), "l"(b));
}
__device__ __forceinline__ void unpack2(unsigned long long v, float& lo, float& hi) {
    unsigned ulo, uhi;
    asm("mov.b64 {%0, %1}, %2;" : "=r"(ulo), "=r"(uhi) : "l"(v));
    lo = __uint_as_float(ulo);
    hi = __uint_as_float(uhi);
}

// ---------------- kernel 1: fold dens_w into conv_w ----------------
// W2[zo][ci][k] folded: g_W2[(ci*27 + k)*16 + zo] = sum_f dens_w[f]*conv_w[f*16+zo][ci][k]
__global__ void fold_kernel(const float* __restrict__ cw, const float* __restrict__ cb,
                            const float* __restrict__ dw, const float* __restrict__ db) {
    int idx = blockIdx.x * blockDim.x + threadIdx.x;
    if (idx < CIN * 27 * Zdim) {
        int zo = idx & 15;
        int k  = (idx >> 4) % 27;
        int ci = idx / (27 * 16);
        float s = 0.f;
#pragma unroll
        for (int f = 0; f < Fdim; ++f)
            s += dw[f] * cw[(((f * Zdim + zo) * CIN) + ci) * 27 + k];
        g_W2[idx] = s;
    }
    if (idx < Zdim) {
        float s = db[0];
#pragma unroll
        for (int f = 0; f < Fdim; ++f) s += dw[f] * cb[f * Zdim + idx];
        g_bias2[idx] = s;
    }
}

// ---------------- kernel 2: folded 3D conv (128 in -> 16 out channels) ----------------
// Block: 32x16 output tile, one t, one 16-ci chunk. 256 threads, each 2 pixels x 16 zo.
#define TILE_X 32
#define TILE_Y 16
#define SIN_STRIDE 35
#define SIN_CI (3 * 18 * SIN_STRIDE)         // 1890 floats per ci
#define SIN_TOTAL (8 * SIN_CI)               // 15120
#define SW_TOTAL (8 * 27 * 16)               // 3456
#define CONV_SMEM_BYTES ((SIN_TOTAL + SW_TOTAL) * 4)

__global__ void __launch_bounds__(256) conv_kernel(const float* __restrict__ vol) {
    extern __shared__ float sm[];
    float* sIn = sm;
    float* sW  = sm + SIN_TOTAL;

    const int tx = threadIdx.x;   // 0..15
    const int ty = threadIdx.y;   // 0..15
    const int tid = ty * 16 + tx;
    const int x0 = blockIdx.x * TILE_X;
    const int y0 = blockIdx.y * TILE_Y;
    const int bz = blockIdx.z;
    const int t = bz >> 3;
    const int chunk = bz & 7;
    const int cibase = chunk * 16;

    unsigned long long accA[8], accB[8];
#pragma unroll
    for (int p = 0; p < 8; ++p) { accA[p] = 0ull; accB[p] = 0ull; }

    for (int s = 0; s < 2; ++s) {
        const int ci0 = cibase + s * 8;
        // cooperative input tile load: 8 ci x 3 t-planes x 18 x 34 (zero-padded)
        for (int e = tid; e < 8 * 3 * 18 * 34; e += 256) {
            int i  = e / (3 * 18 * 34);
            int r  = e % (3 * 18 * 34);
            int kd = r / (18 * 34);
            int r2 = r % (18 * 34);
            int yy = r2 / 34;
            int xx = r2 % 34;
            int ci = ci0 + i;
            int f = ci >> 4, z = ci & 15;
            int gt = t + kd - 1;
            int gy = y0 + yy - 1;
            int gx = x0 + xx - 1;
            float v = 0.f;
            if (gt >= 0 && gt < Tdim && gy >= 0 && gy < Ydim && gx >= 0 && gx < Xdim)
                v = vol[(((size_t)(f * Tdim + gt) * Zdim + z) * Ydim + gy) * Xdim + gx];
            sIn[((i * 3 + kd) * 18 + yy) * SIN_STRIDE + xx] = v;
        }
        // weights for this 8-ci sub-chunk (contiguous in g_W2)
        const float* W2g = g_W2 + (size_t)ci0 * 27 * 16;
        for (int e = tid; e < SW_TOTAL; e += 256) sW[e] = W2g[e];
        __syncthreads();

#pragma unroll 1
        for (int i = 0; i < 8; ++i) {
            const float* base_i = sIn + i * SIN_CI;
#pragma unroll
            for (int kd = 0; kd < 3; ++kd) {
#pragma unroll
                for (int kh = 0; kh < 3; ++kh) {
                    const float* row = base_i + (kd * 18 + ty + kh) * SIN_STRIDE + 2 * tx;
#pragma unroll
                    for (int kw = 0; kw < 3; ++kw) {
                        float a0 = row[kw];
                        float a1 = row[kw + 1];
                        unsigned long long ua0 = pack2(a0);
                        unsigned long long ua1 = pack2(a1);
                        const unsigned long long* wp =
                            (const unsigned long long*)(sW + (i * 27 + (kd * 9 + kh * 3 + kw)) * 16);
#pragma unroll
                        for (int p = 0; p < 8; ++p) {
                            unsigned long long w = wp[p];
                            fma2(accA[p], ua0, w);
                            fma2(accB[p], ua1, w);
                        }
                    }
                }
            }
        }
        __syncthreads();
    }

    // write partial sums
    float* outp = g_Spart[chunk];
    const int yy = y0 + ty;
    const int xA = x0 + 2 * tx;
#pragma unroll
    for (int p = 0; p < 8; ++p) {
        float a0, a1, b0, b1;
        unpack2(accA[p], a0, a1);  // (zo=2p, zo=2p+1) for pixel xA
        unpack2(accB[p], b0, b1);  // for pixel xA+1
        int zo = 2 * p;
        size_t o0 = (((size_t)t * Zdim + zo) * Ydim + yy) * Xdim + xA;
        size_t o1 = (((size_t)t * Zdim + zo + 1) * Ydim + yy) * Xdim + xA;
        outp[o0] = a0; outp[o0 + 1] = b0;
        outp[o1] = a1; outp[o1 + 1] = b1;
    }
}

// ---------------- kernel 3: combine partials + bias ----------------
__global__ void combine_kernel() {
    int idx = blockIdx.x * blockDim.x + threadIdx.x;
    if (idx >= VOXALL) return;
    int zo = (idx / (Ydim * Xdim)) % Zdim;
    float s = g_bias2[zo];
#pragma unroll
    for (int c = 0; c < 8; ++c) s += g_Spart[c][idx];
    g_S[idx] = s;
}

// ---------------- kernel 4: expand to 8-corner fp16 cells ----------------
__global__ void expand_kernel() {
    int idx = blockIdx.x * blockDim.x + threadIdx.x;
    if (idx >= VOXALL) return;
    int x = idx % Xdim;
    int y = (idx / Xdim) % Ydim;
    int z = (idx / (Xdim * Ydim)) % Zdim;
    int t = idx / (Xdim * Ydim * Zdim);
    int x1 = min(x + 1, Xdim - 1);
    int y1 = min(y + 1, Ydim - 1);
    int z1 = min(z + 1, Zdim - 1);
    const float* St = g_S + (size_t)t * VOXT;
#define AT(zz, yy, xx) St[((zz) * Ydim + (yy)) * Xdim + (xx)]
    __half2 h01 = __floats2half2_rn(AT(z,  y,  x), AT(z,  y,  x1));
    __half2 h23 = __floats2half2_rn(AT(z,  y1, x), AT(z,  y1, x1));
    __half2 h45 = __floats2half2_rn(AT(z1, y,  x), AT(z1, y,  x1));
    __half2 h67 = __floats2half2_rn(AT(z1, y1, x), AT(z1, y1, x1));
#undef AT
    uint4 u;
    u.x = *reinterpret_cast<unsigned*>(&h01);
    u.y = *reinterpret_cast<unsigned*>(&h23);
    u.z = *reinterpret_cast<unsigned*>(&h45);
    u.w = *reinterpret_cast<unsigned*>(&h67);
    g_S8[idx] = u;
}

// ---------------- ray box intersection (shared by minmax + render) ----------------
__device__ __forceinline__ void ray_near_far(float ox, float oy, float oz,
                                             float dx, float dy, float dz,
                                             float& nearv, float& farv) {
    float t1 = (0.f - ox) / dx, t2 = (1.f - ox) / dx;
    float nv = fminf(t1, t2), fv = fmaxf(t1, t2);
    t1 = (0.f - oy) / dy; t2 = (1.f - oy) / dy;
    nv = fmaxf(nv, fminf(t1, t2)); fv = fminf(fv, fmaxf(t1, t2));
    t1 = (0.f - oz) / dz; t2 = (1.f - oz) / dz;
    nv = fmaxf(nv, fminf(t1, t2)); fv = fminf(fv, fmaxf(t1, t2));
    nv = fmaxf(nv, 0.01f);
    fv = fmaxf(fv, nv + 1e-6f);
    nearv = nv; farv = fv;
}

// ---------------- kernel 5a: init clip bounds ----------------
__global__ void init_minmax_kernel() {
    int i = threadIdx.x;
    if (i < Tdim) { g_lo[i] = 3.4e38f; g_hi[i] = 0.f; }
}

// ---------------- kernel 5b: global per-t min(starts)/max(starts) ----------------
// ref does jnp.clip(depth, starts.min(), starts.max()) with GLOBAL (all-ray) bounds.
__global__ void __launch_bounds__(256) minmax_kernel(const float* __restrict__ ro,
                                                     const float* __restrict__ rd) {
    __shared__ float slo[256], shi[256];
    int r = blockIdx.x * 256 + threadIdx.x;   // grid exactly covers Tdim*NRAYS
    int t = r / NRAYS;
    float ox = ro[r * 3 + 0], oy = ro[r * 3 + 1], oz = ro[r * 3 + 2];
    float dx = rd[r * 3 + 0], dy = rd[r * 3 + 1], dz = rd[r * 3 + 2];
    float nearv, farv;
    ray_near_far(ox, oy, oz, dx, dy, dz, nearv, farv);
    float step = (farv - nearv) * (1.f / 128.f);
    float hi = nearv + 127.f * step;
    slo[threadIdx.x] = nearv;
    shi[threadIdx.x] = hi;
    __syncthreads();
    for (int s = 128; s > 0; s >>= 1) {
        if (threadIdx.x < s) {
            slo[threadIdx.x] = fminf(slo[threadIdx.x], slo[threadIdx.x + s]);
            shi[threadIdx.x] = fmaxf(shi[threadIdx.x], shi[threadIdx.x + s]);
        }
        __syncthreads();
    }
    if (threadIdx.x == 0) {
        // all values positive -> int-bit compare is order-preserving; min/max are
        // order-independent -> deterministic.
        atomicMin((int*)&g_lo[t], __float_as_int(slo[0]));
        atomicMax((int*)&g_hi[t], __float_as_int(shi[0]));
    }
}

// ---------------- kernel 6: volume rendering ----------------
__global__ void __launch_bounds__(256) render_kernel(const float* __restrict__ ro,
                                                     const float* __restrict__ rd,
                                                     float* __restrict__ out) {
    int r = blockIdx.x * 256 + threadIdx.x;
    int t = r / NRAYS;
    float ox = ro[r * 3 + 0], oy = ro[r * 3 + 1], oz = ro[r * 3 + 2];
    float dx = rd[r * 3 + 0], dy = rd[r * 3 + 1], dz = rd[r * 3 + 2];
    float nearv, farv;
    ray_near_far(ox, oy, oz, dx, dy, dz, nearv, farv);
    float step = (farv - nearv) * (1.f / 128.f);

    const uint4* S8t = g_S8 + (size_t)t * VOXT;
    float Tr = 1.f, sw = 0.f, swd = 0.f;

#pragma unroll 4
    for (int k = 0; k < KSAMP; ++k) {
        float tm = nearv + ((float)k + 0.5f) * step;
        float px = ox + dx * tm;
        float py = oy + dy * tm;
        float pz = oz + dz * tm;
        float gx = fminf(fmaxf(px, 0.f), 1.f) * 95.f;
        float gy = fminf(fmaxf(py, 0.f), 1.f) * 95.f;
        float gz = fminf(fmaxf(pz, 0.f), 1.f) * 15.f;
        float fx0 = floorf(gx), fy0 = floorf(gy), fz0 = floorf(gz);
        int ix = (int)fx0, iy = (int)fy0, iz = (int)fz0;
        float fx = gx - fx0, fy = gy - fy0, fz = gz - fz0;

        uint4 u = __ldg(&S8t[(iz * Ydim + iy) * Xdim + ix]);
        float2 c00 = __half22float2(*reinterpret_cast<const __half2*>(&u.x)); // z0 y0
        float2 c01 = __half22float2(*reinterpret_cast<const __half2*>(&u.y)); // z0 y1
        float2 c10 = __half22float2(*reinterpret_cast<const __half2*>(&u.z)); // z1 y0
        float2 c11 = __half22float2(*reinterpret_cast<const __half2*>(&u.w)); // z1 y1

        float a0 = c00.x + fx * (c00.y - c00.x);
        float a1 = c01.x + fx * (c01.y - c01.x);
        float b0 = c10.x + fx * (c10.y - c10.x);
        float b1 = c11.x + fx * (c11.y - c11.x);
        float va = a0 + fy * (a1 - a0);
        float vb = b0 + fy * (b1 - b0);
        float s  = va + fz * (vb - va);

        // softplus (matches jax logaddexp(x,0) form)
        float dens = fmaxf(s, 0.f) + log1pf(__expf(-fabsf(s)));
        float dd = dens * step;
        float e = __expf(-dd);
        float w = Tr * (1.f - e);
        sw  += w;
        swd += w * (nearv + (float)k * step);
        Tr  *= e;
    }

    float depth = swd / (sw + 1e-10f);
    depth = fminf(fmaxf(depth, g_lo[t]), g_hi[t]);
    out[r] = depth;
}

// ---------------- launch ----------------
extern "C" void kernel_launch(void* const* d_in, const int* in_sizes, int n_in,
                              void* d_out, int out_size) {
    (void)in_sizes; (void)n_in; (void)out_size;
    const float* vol = (const float*)d_in[0];
    const float* ro  = (const float*)d_in[1];
    const float* rd  = (const float*)d_in[2];
    const float* cw  = (const float*)d_in[3];
    const float* cb  = (const float*)d_in[4];
    const float* dw  = (const float*)d_in[5];
    const float* db  = (const float*)d_in[6];
    float* out = (float*)d_out;

    cudaFuncSetAttribute(conv_kernel, cudaFuncAttributeMaxDynamicSharedMemorySize,
                         CONV_SMEM_BYTES);

    fold_kernel<<<(CIN * 27 * Zdim + 255) / 256, 256>>>(cw, cb, dw, db);

    dim3 cgrid(Xdim / TILE_X, Ydim / TILE_Y, Tdim * 8);  // (3, 6, 40) = 720 blocks
    dim3 cblk(16, 16);
    conv_kernel<<<cgrid, cblk, CONV_SMEM_BYTES>>>(vol);

    combine_kernel<<<(VOXALL + 255) / 256, 256>>>();
    expand_kernel<<<(VOXALL + 255) / 256, 256>>>();

    init_minmax_kernel<<<1, 32>>>();
    minmax_kernel<<<(Tdim * NRAYS) / 256, 256>>>(ro, rd);
    render_kernel<<<(Tdim * NRAYS) / 256, 256>>>(ro, rd, out);
}

// round 13
// speedup vs baseline: 1.0493x; 1.0493x over previous
#include <cuda_runtime.h>
#include <cuda_fp16.h>

// ---------------- problem constants ----------------
#define Fdim   8
#define Tdim   5
#define Zdim   16
#define Ydim   96
#define Xdim   96
#define NRAYS  32768
#define KSAMP  128
#define CIN    128               // Fdim*Zdim
#define VOXT   (Zdim*Ydim*Xdim)  // 147456 per t
#define VOXALL (Tdim*VOXT)       // 737280

// ---------------- scratch (device globals; no allocation) ----------------
__device__ float g_W2[CIN * 27 * Zdim];   // folded weights [ci][k][zo]
__device__ float g_bias2[Zdim];
__device__ float g_Spart[8][VOXALL];      // per-ci-chunk partial conv outputs
__device__ float g_S[VOXALL];             // combined density pre-activation volume
__device__ uint4 g_S8[VOXALL];            // 8 fp16 trilinear corners per cell
__device__ float g_lo[Tdim], g_hi[Tdim];  // global per-t clip bounds

// ---------------- f32x2 helpers ----------------
__device__ __forceinline__ unsigned long long pack2(float x) {
    unsigned long long r;
    unsigned u = __float_as_uint(x);
    asm("mov.b64 %0, {%1, %1};" : "=l"(r) : "r"(u));
    return r;
}
__device__ __forceinline__ void fma2(unsigned long long& c, unsigned long long a,
                                     unsigned long long b) {
    asm("fma.rn.f32x2 %0, %1, %2, %0;" : "+l"(c) : "l"(a), "l"(b));
}
__device__ __forceinline__ void unpack2(unsigned long long v, float& lo, float& hi) {
    unsigned ulo, uhi;
    asm("mov.b64 {%0, %1}, %2;" : "=r"(ulo), "=r"(uhi) : "l"(v));
    lo = __uint_as_float(ulo);
    hi = __uint_as_float(uhi);
}

// ---------------- kernel 1: fold dens_w into conv_w ----------------
// W2[zo][ci][k] folded: g_W2[(ci*27 + k)*16 + zo] = sum_f dens_w[f]*conv_w[f*16+zo][ci][k]
__global__ void fold_kernel(const float* __restrict__ cw, const float* __restrict__ cb,
                            const float* __restrict__ dw, const float* __restrict__ db) {
    int idx = blockIdx.x * blockDim.x + threadIdx.x;
    if (idx < CIN * 27 * Zdim) {
        int zo = idx & 15;
        int k  = (idx >> 4) % 27;
        int ci = idx / (27 * 16);
        float s = 0.f;
#pragma unroll
        for (int f = 0; f < Fdim; ++f)
            s += dw[f] * cw[(((f * Zdim + zo) * CIN) + ci) * 27 + k];
        g_W2[idx] = s;
    }
    if (idx < Zdim) {
        float s = db[0];
#pragma unroll
        for (int f = 0; f < Fdim; ++f) s += dw[f] * cb[f * Zdim + idx];
        g_bias2[idx] = s;
    }
}

// ---------------- kernel 2: folded 3D conv (128 in -> 16 out channels) ----------------
// Block: 32x16 output tile, one t, one 16-ci chunk. 256 threads, each 2 pixels x 16 zo.
#define TILE_X 32
#define TILE_Y 16
#define SIN_STRIDE 35
#define SIN_CI (3 * 18 * SIN_STRIDE)         // 1890 floats per ci
#define SIN_TOTAL (8 * SIN_CI)               // 15120
#define SW_TOTAL (8 * 27 * 16)               // 3456
#define CONV_SMEM_BYTES ((SIN_TOTAL + SW_TOTAL) * 4)

__global__ void __launch_bounds__(256) conv_kernel(const float* __restrict__ vol) {
    extern __shared__ float sm[];
    float* sIn = sm;
    float* sW  = sm + SIN_TOTAL;

    const int tx = threadIdx.x;   // 0..15
    const int ty = threadIdx.y;   // 0..15
    const int tid = ty * 16 + tx;
    const int x0 = blockIdx.x * TILE_X;
    const int y0 = blockIdx.y * TILE_Y;
    const int bz = blockIdx.z;
    const int t = bz >> 3;
    const int chunk = bz & 7;
    const int cibase = chunk * 16;

    unsigned long long accA[8], accB[8];
#pragma unroll
    for (int p = 0; p < 8; ++p) { accA[p] = 0ull; accB[p] = 0ull; }

    for (int s = 0; s < 2; ++s) {
        const int ci0 = cibase + s * 8;
        // cooperative input tile load: 8 ci x 3 t-planes x 18 x 34 (zero-padded)
        for (int e = tid; e < 8 * 3 * 18 * 34; e += 256) {
            int i  = e / (3 * 18 * 34);
            int r  = e % (3 * 18 * 34);
            int kd = r / (18 * 34);
            int r2 = r % (18 * 34);
            int yy = r2 / 34;
            int xx = r2 % 34;
            int ci = ci0 + i;
            int f = ci >> 4, z = ci & 15;
            int gt = t + kd - 1;
            int gy = y0 + yy - 1;
            int gx = x0 + xx - 1;
            float v = 0.f;
            if (gt >= 0 && gt < Tdim && gy >= 0 && gy < Ydim && gx >= 0 && gx < Xdim)
                v = vol[(((size_t)(f * Tdim + gt) * Zdim + z) * Ydim + gy) * Xdim + gx];
            sIn[((i * 3 + kd) * 18 + yy) * SIN_STRIDE + xx] = v;
        }
        // weights for this 8-ci sub-chunk (contiguous in g_W2)
        const float* W2g = g_W2 + (size_t)ci0 * 27 * 16;
        for (int e = tid; e < SW_TOTAL; e += 256) sW[e] = W2g[e];
        __syncthreads();

#pragma unroll 1
        for (int i = 0; i < 8; ++i) {
            const float* base_i = sIn + i * SIN_CI;
#pragma unroll
            for (int kd = 0; kd < 3; ++kd) {
#pragma unroll
                for (int kh = 0; kh < 3; ++kh) {
                    const float* row = base_i + (kd * 18 + ty + kh) * SIN_STRIDE + 2 * tx;
#pragma unroll
                    for (int kw = 0; kw < 3; ++kw) {
                        float a0 = row[kw];
                        float a1 = row[kw + 1];
                        unsigned long long ua0 = pack2(a0);
                        unsigned long long ua1 = pack2(a1);
                        const unsigned long long* wp =
                            (const unsigned long long*)(sW + (i * 27 + (kd * 9 + kh * 3 + kw)) * 16);
#pragma unroll
                        for (int p = 0; p < 8; ++p) {
                            unsigned long long w = wp[p];
                            fma2(accA[p], ua0, w);
                            fma2(accB[p], ua1, w);
                        }
                    }
                }
            }
        }
        __syncthreads();
    }

    // write partial sums
    float* outp = g_Spart[chunk];
    const int yy = y0 + ty;
    const int xA = x0 + 2 * tx;
#pragma unroll
    for (int p = 0; p < 8; ++p) {
        float a0, a1, b0, b1;
        unpack2(accA[p], a0, a1);  // (zo=2p, zo=2p+1) for pixel xA
        unpack2(accB[p], b0, b1);  // for pixel xA+1
        int zo = 2 * p;
        size_t o0 = (((size_t)t * Zdim + zo) * Ydim + yy) * Xdim + xA;
        size_t o1 = (((size_t)t * Zdim + zo + 1) * Ydim + yy) * Xdim + xA;
        outp[o0] = a0; outp[o0 + 1] = b0;
        outp[o1] = a1; outp[o1 + 1] = b1;
    }
}

// ---------------- kernel 3: combine partials + bias ----------------
__global__ void combine_kernel() {
    int idx = blockIdx.x * blockDim.x + threadIdx.x;
    if (idx >= VOXALL) return;
    int zo = (idx / (Ydim * Xdim)) % Zdim;
    float s = g_bias2[zo];
#pragma unroll
    for (int c = 0; c < 8; ++c) s += g_Spart[c][idx];
    g_S[idx] = s;
}

// ---------------- kernel 4: expand to 8-corner fp16 cells ----------------
__global__ void expand_kernel() {
    int idx = blockIdx.x * blockDim.x + threadIdx.x;
    if (idx >= VOXALL) return;
    int x = idx % Xdim;
    int y = (idx / Xdim) % Ydim;
    int z = (idx / (Xdim * Ydim)) % Zdim;
    int t = idx / (Xdim * Ydim * Zdim);
    int x1 = min(x + 1, Xdim - 1);
    int y1 = min(y + 1, Ydim - 1);
    int z1 = min(z + 1, Zdim - 1);
    const float* St = g_S + (size_t)t * VOXT;
#define AT(zz, yy, xx) St[((zz) * Ydim + (yy)) * Xdim + (xx)]
    __half2 h01 = __floats2half2_rn(AT(z,  y,  x), AT(z,  y,  x1));
    __half2 h23 = __floats2half2_rn(AT(z,  y1, x), AT(z,  y1, x1));
    __half2 h45 = __floats2half2_rn(AT(z1, y,  x), AT(z1, y,  x1));
    __half2 h67 = __floats2half2_rn(AT(z1, y1, x), AT(z1, y1, x1));
#undef AT
    uint4 u;
    u.x = *reinterpret_cast<unsigned*>(&h01);
    u.y = *reinterpret_cast<unsigned*>(&h23);
    u.z = *reinterpret_cast<unsigned*>(&h45);
    u.w = *reinterpret_cast<unsigned*>(&h67);
    g_S8[idx] = u;
}

// ---------------- ray box intersection (shared by minmax + render) ----------------
__device__ __forceinline__ void ray_near_far(float ox, float oy, float oz,
                                             float dx, float dy, float dz,
                                             float& nearv, float& farv) {
    float t1 = (0.f - ox) / dx, t2 = (1.f - ox) / dx;
    float nv = fminf(t1, t2), fv = fmaxf(t1, t2);
    t1 = (0.f - oy) / dy; t2 = (1.f - oy) / dy;
    nv = fmaxf(nv, fminf(t1, t2)); fv = fminf(fv, fmaxf(t1, t2));
    t1 = (0.f - oz) / dz; t2 = (1.f - oz) / dz;
    nv = fmaxf(nv, fminf(t1, t2)); fv = fminf(fv, fmaxf(t1, t2));
    nv = fmaxf(nv, 0.01f);
    fv = fmaxf(fv, nv + 1e-6f);
    nearv = nv; farv = fv;
}

// ---------------- kernel 5a: init clip bounds ----------------
__global__ void init_minmax_kernel() {
    int i = threadIdx.x;
    if (i < Tdim) { g_lo[i] = 3.4e38f; g_hi[i] = 0.f; }
}

// ---------------- kernel 5b: global per-t min(starts)/max(starts) ----------------
// ref does jnp.clip(depth, starts.min(), starts.max()) with GLOBAL (all-ray) bounds.
__global__ void __launch_bounds__(256) minmax_kernel(const float* __restrict__ ro,
                                                     const float* __restrict__ rd) {
    __shared__ float slo[256], shi[256];
    int r = blockIdx.x * 256 + threadIdx.x;   // grid exactly covers Tdim*NRAYS
    int t = r / NRAYS;
    float ox = ro[r * 3 + 0], oy = ro[r * 3 + 1], oz = ro[r * 3 + 2];
    float dx = rd[r * 3 + 0], dy = rd[r * 3 + 1], dz = rd[r * 3 + 2];
    float nearv, farv;
    ray_near_far(ox, oy, oz, dx, dy, dz, nearv, farv);
    float step = (farv - nearv) * (1.f / 128.f);
    float hi = nearv + 127.f * step;
    slo[threadIdx.x] = nearv;
    shi[threadIdx.x] = hi;
    __syncthreads();
    for (int s = 128; s > 0; s >>= 1) {
        if (threadIdx.x < s) {
            slo[threadIdx.x] = fminf(slo[threadIdx.x], slo[threadIdx.x + s]);
            shi[threadIdx.x] = fmaxf(shi[threadIdx.x], shi[threadIdx.x + s]);
        }
        __syncthreads();
    }
    if (threadIdx.x == 0) {
        // all values positive -> int-bit compare is order-preserving; min/max are
        // order-independent -> deterministic.
        atomicMin((int*)&g_lo[t], __float_as_int(slo[0]));
        atomicMax((int*)&g_hi[t], __float_as_int(shi[0]));
    }
}

// ---------------- kernel 6: volume rendering ----------------
__global__ void __launch_bounds__(256) render_kernel(const float* __restrict__ ro,
                                                     const float* __restrict__ rd,
                                                     float* __restrict__ out) {
    int r = blockIdx.x * 256 + threadIdx.x;
    int t = r / NRAYS;
    float ox = ro[r * 3 + 0], oy = ro[r * 3 + 1], oz = ro[r * 3 + 2];
    float dx = rd[r * 3 + 0], dy = rd[r * 3 + 1], dz = rd[r * 3 + 2];
    float nearv, farv;
    ray_near_far(ox, oy, oz, dx, dy, dz, nearv, farv);
    float step = (farv - nearv) * (1.f / 128.f);

    const uint4* S8t = g_S8 + (size_t)t * VOXT;
    float Tr = 1.f, sw = 0.f, swd = 0.f;

#pragma unroll 4
    for (int k = 0; k < KSAMP; ++k) {
        float tm = nearv + ((float)k + 0.5f) * step;
        float px = ox + dx * tm;
        float py = oy + dy * tm;
        float pz = oz + dz * tm;
        float gx = fminf(fmaxf(px, 0.f), 1.f) * 95.f;
        float gy = fminf(fmaxf(py, 0.f), 1.f) * 95.f;
        float gz = fminf(fmaxf(pz, 0.f), 1.f) * 15.f;
        float fx0 = floorf(gx), fy0 = floorf(gy), fz0 = floorf(gz);
        int ix = (int)fx0, iy = (int)fy0, iz = (int)fz0;
        float fx = gx - fx0, fy = gy - fy0, fz = gz - fz0;

        uint4 u = __ldg(&S8t[(iz * Ydim + iy) * Xdim + ix]);
        float2 c00 = __half22float2(*reinterpret_cast<const __half2*>(&u.x)); // z0 y0
        float2 c01 = __half22float2(*reinterpret_cast<const __half2*>(&u.y)); // z0 y1
        float2 c10 = __half22float2(*reinterpret_cast<const __half2*>(&u.z)); // z1 y0
        float2 c11 = __half22float2(*reinterpret_cast<const __half2*>(&u.w)); // z1 y1

        float a0 = c00.x + fx * (c00.y - c00.x);
        float a1 = c01.x + fx * (c01.y - c01.x);
        float b0 = c10.x + fx * (c10.y - c10.x);
        float b1 = c11.x + fx * (c11.y - c11.x);
        float va = a0 + fy * (a1 - a0);
        float vb = b0 + fy * (b1 - b0);
        float s  = va + fz * (vb - va);

        // softplus (matches jax logaddexp(x,0) form)
        float dens = fmaxf(s, 0.f) + log1pf(__expf(-fabsf(s)));
        float dd = dens * step;
        float e = __expf(-dd);
        float w = Tr * (1.f - e);
        sw  += w;
        swd += w * (nearv + (float)k * step);
        Tr  *= e;
    }

    float depth = swd / (sw + 1e-10f);
    depth = fminf(fmaxf(depth, g_lo[t]), g_hi[t]);
    out[r] = depth;
}

// ---------------- launch ----------------
extern "C" void kernel_launch(void* const* d_in, const int* in_sizes, int n_in,
                              void* d_out, int out_size) {
    (void)in_sizes; (void)n_in; (void)out_size;
    const float* vol = (const float*)d_in[0];
    const float* ro  = (const float*)d_in[1];
    const float* rd  = (const float*)d_in[2];
    const float* cw  = (const float*)d_in[3];
    const float* cb  = (const float*)d_in[4];
    const float* dw  = (const float*)d_in[5];
    const float* db  = (const float*)d_in[6];
    float* out = (float*)d_out;

    cudaFuncSetAttribute(conv_kernel, cudaFuncAttributeMaxDynamicSharedMemorySize,
                         CONV_SMEM_BYTES);

    fold_kernel<<<(CIN * 27 * Zdim + 255) / 256, 256>>>(cw, cb, dw, db);

    dim3 cgrid(Xdim / TILE_X, Ydim / TILE_Y, Tdim * 8);  // (3, 6, 40) = 720 blocks
    dim3 cblk(16, 16);
    conv_kernel<<<cgrid, cblk, CONV_SMEM_BYTES>>>(vol);

    combine_kernel<<<(VOXALL + 255) / 256, 256>>>();
    expand_kernel<<<(VOXALL + 255) / 256, 256>>>();

    init_minmax_kernel<<<1, 32>>>();
    minmax_kernel<<<(Tdim * NRAYS) / 256, 256>>>(ro, rd);
    render_kernel<<<(Tdim * NRAYS) / 256, 256>>>(ro, rd, out);
}

// round 14
// speedup vs baseline: 1.0506x; 1.0013x over previous
#include <cuda_runtime.h>
#include <cuda_fp16.h>

// ---------------- problem constants ----------------
#define Fdim   8
#define Tdim   5
#define Zdim   16
#define Ydim   96
#define Xdim   96
#define NRAYS  32768
#define KSAMP  128
#define CIN    128               // Fdim*Zdim
#define VOXT   (Zdim*Ydim*Xdim)  // 147456 per t
#define VOXALL (Tdim*VOXT)       // 737280

// ---------------- scratch (device globals; no allocation) ----------------
__device__ float g_W2[CIN * 27 * Zdim];   // folded weights [ci][k][zo]
__device__ float g_bias2[Zdim];
__device__ float g_Spart[8][VOXALL];      // per-ci-chunk partial conv outputs
__device__ float g_S[VOXALL];             // combined density pre-activation volume
__device__ uint4 g_S8[VOXALL];            // 8 fp16 trilinear corners per cell
__device__ float g_lo[Tdim], g_hi[Tdim];  // global per-t clip bounds

// ---------------- f32x2 helpers ----------------
__device__ __forceinline__ unsigned long long pack2(float x) {
    unsigned long long r;
    unsigned u = __float_as_uint(x);
    asm("mov.b64 %0, {%1, %1};" : "=l"(r) : "r"(u));
    return r;
}
__device__ __forceinline__ void fma2(unsigned long long& c, unsigned long long a,
                                     unsigned long long b) {
    asm("fma.rn.f32x2 %0, %1, %2, %0;" : "+l"(c) : "l"(a), "l"(b));
}
__device__ __forceinline__ void unpack2(unsigned long long v, float& lo, float& hi) {
    unsigned ulo, uhi;
    asm("mov.b64 {%0, %1}, %2;" : "=r"(ulo), "=r"(uhi) : "l"(v));
    lo = __uint_as_float(ulo);
    hi = __uint_as_float(uhi);
}

// ---------------- kernel 1: fold dens_w into conv_w ----------------
// W2[zo][ci][k] folded: g_W2[(ci*27 + k)*16 + zo] = sum_f dens_w[f]*conv_w[f*16+zo][ci][k]
__global__ void fold_kernel(const float* __restrict__ cw, const float* __restrict__ cb,
                            const float* __restrict__ dw, const float* __restrict__ db) {
    int idx = blockIdx.x * blockDim.x + threadIdx.x;
    if (idx < CIN * 27 * Zdim) {
        int zo = idx & 15;
        int k  = (idx >> 4) % 27;
        int ci = idx / (27 * 16);
        float s = 0.f;
#pragma unroll
        for (int f = 0; f < Fdim; ++f)
            s += dw[f] * cw[(((f * Zdim + zo) * CIN) + ci) * 27 + k];
        g_W2[idx] = s;
    }
    if (idx < Zdim) {
        float s = db[0];
#pragma unroll
        for (int f = 0; f < Fdim; ++f) s += dw[f] * cb[f * Zdim + idx];
        g_bias2[idx] = s;
    }
}

// ---------------- kernel 2: folded 3D conv (128 in -> 16 out channels) ----------------
// Block: 32x16 output tile, one t, one 16-ci chunk. 256 threads, each 2 pixels x 16 zo.
#define TILE_X 32
#define TILE_Y 16
#define SIN_STRIDE 35
#define SIN_CI (3 * 18 * SIN_STRIDE)         // 1890 floats per ci
#define SIN_TOTAL (8 * SIN_CI)               // 15120
#define SW_TOTAL (8 * 27 * 16)               // 3456
#define CONV_SMEM_BYTES ((SIN_TOTAL + SW_TOTAL) * 4)

__global__ void __launch_bounds__(256) conv_kernel(const float* __restrict__ vol) {
    extern __shared__ float sm[];
    float* sIn = sm;
    float* sW  = sm + SIN_TOTAL;

    const int tx = threadIdx.x;   // 0..15
    const int ty = threadIdx.y;   // 0..15
    const int tid = ty * 16 + tx;
    const int x0 = blockIdx.x * TILE_X;
    const int y0 = blockIdx.y * TILE_Y;
    const int bz = blockIdx.z;
    const int t = bz >> 3;
    const int chunk = bz & 7;
    const int cibase = chunk * 16;

    unsigned long long accA[8], accB[8];
#pragma unroll
    for (int p = 0; p < 8; ++p) { accA[p] = 0ull; accB[p] = 0ull; }

    for (int s = 0; s < 2; ++s) {
        const int ci0 = cibase + s * 8;
        // cooperative input tile load: 8 ci x 3 t-planes x 18 x 34 (zero-padded)
        for (int e = tid; e < 8 * 3 * 18 * 34; e += 256) {
            int i  = e / (3 * 18 * 34);
            int r  = e % (3 * 18 * 34);
            int kd = r / (18 * 34);
            int r2 = r % (18 * 34);
            int yy = r2 / 34;
            int xx = r2 % 34;
            int ci = ci0 + i;
            int f = ci >> 4, z = ci & 15;
            int gt = t + kd - 1;
            int gy = y0 + yy - 1;
            int gx = x0 + xx - 1;
            float v = 0.f;
            if (gt >= 0 && gt < Tdim && gy >= 0 && gy < Ydim && gx >= 0 && gx < Xdim)
                v = vol[(((size_t)(f * Tdim + gt) * Zdim + z) * Ydim + gy) * Xdim + gx];
            sIn[((i * 3 + kd) * 18 + yy) * SIN_STRIDE + xx] = v;
        }
        // weights for this 8-ci sub-chunk (contiguous in g_W2)
        const float* W2g = g_W2 + (size_t)ci0 * 27 * 16;
        for (int e = tid; e < SW_TOTAL; e += 256) sW[e] = W2g[e];
        __syncthreads();

#pragma unroll 1
        for (int i = 0; i < 8; ++i) {
            const float* base_i = sIn + i * SIN_CI;
#pragma unroll
            for (int kd = 0; kd < 3; ++kd) {
#pragma unroll
                for (int kh = 0; kh < 3; ++kh) {
                    const float* row = base_i + (kd * 18 + ty + kh) * SIN_STRIDE + 2 * tx;
#pragma unroll
                    for (int kw = 0; kw < 3; ++kw) {
                        float a0 = row[kw];
                        float a1 = row[kw + 1];
                        unsigned long long ua0 = pack2(a0);
                        unsigned long long ua1 = pack2(a1);
                        const unsigned long long* wp =
                            (const unsigned long long*)(sW + (i * 27 + (kd * 9 + kh * 3 + kw)) * 16);
#pragma unroll
                        for (int p = 0; p < 8; ++p) {
                            unsigned long long w = wp[p];
                            fma2(accA[p], ua0, w);
                            fma2(accB[p], ua1, w);
                        }
                    }
                }
            }
        }
        __syncthreads();
    }

    // write partial sums
    float* outp = g_Spart[chunk];
    const int yy = y0 + ty;
    const int xA = x0 + 2 * tx;
#pragma unroll
    for (int p = 0; p < 8; ++p) {
        float a0, a1, b0, b1;
        unpack2(accA[p], a0, a1);  // (zo=2p, zo=2p+1) for pixel xA
        unpack2(accB[p], b0, b1);  // for pixel xA+1
        int zo = 2 * p;
        size_t o0 = (((size_t)t * Zdim + zo) * Ydim + yy) * Xdim + xA;
        size_t o1 = (((size_t)t * Zdim + zo + 1) * Ydim + yy) * Xdim + xA;
        outp[o0] = a0; outp[o0 + 1] = b0;
        outp[o1] = a1; outp[o1 + 1] = b1;
    }
}

// ---------------- kernel 3: combine partials + bias ----------------
__global__ void combine_kernel() {
    int idx = blockIdx.x * blockDim.x + threadIdx.x;
    if (idx >= VOXALL) return;
    int zo = (idx / (Ydim * Xdim)) % Zdim;
    float s = g_bias2[zo];
#pragma unroll
    for (int c = 0; c < 8; ++c) s += g_Spart[c][idx];
    g_S[idx] = s;
}

// ---------------- kernel 4: expand to 8-corner fp16 cells ----------------
__global__ void expand_kernel() {
    int idx = blockIdx.x * blockDim.x + threadIdx.x;
    if (idx >= VOXALL) return;
    int x = idx % Xdim;
    int y = (idx / Xdim) % Ydim;
    int z = (idx / (Xdim * Ydim)) % Zdim;
    int t = idx / (Xdim * Ydim * Zdim);
    int x1 = min(x + 1, Xdim - 1);
    int y1 = min(y + 1, Ydim - 1);
    int z1 = min(z + 1, Zdim - 1);
    const float* St = g_S + (size_t)t * VOXT;
#define AT(zz, yy, xx) St[((zz) * Ydim + (yy)) * Xdim + (xx)]
    __half2 h01 = __floats2half2_rn(AT(z,  y,  x), AT(z,  y,  x1));
    __half2 h23 = __floats2half2_rn(AT(z,  y1, x), AT(z,  y1, x1));
    __half2 h45 = __floats2half2_rn(AT(z1, y,  x), AT(z1, y,  x1));
    __half2 h67 = __floats2half2_rn(AT(z1, y1, x), AT(z1, y1, x1));
#undef AT
    uint4 u;
    u.x = *reinterpret_cast<unsigned*>(&h01);
    u.y = *reinterpret_cast<unsigned*>(&h23);
    u.z = *reinterpret_cast<unsigned*>(&h45);
    u.w = *reinterpret_cast<unsigned*>(&h67);
    g_S8[idx] = u;
}

// ---------------- ray box intersection (shared by minmax + render) ----------------
__device__ __forceinline__ void ray_near_far(float ox, float oy, float oz,
                                             float dx, float dy, float dz,
                                             float& nearv, float& farv) {
    float t1 = (0.f - ox) / dx, t2 = (1.f - ox) / dx;
    float nv = fminf(t1, t2), fv = fmaxf(t1, t2);
    t1 = (0.f - oy) / dy; t2 = (1.f - oy) / dy;
    nv = fmaxf(nv, fminf(t1, t2)); fv = fminf(fv, fmaxf(t1, t2));
    t1 = (0.f - oz) / dz; t2 = (1.f - oz) / dz;
    nv = fmaxf(nv, fminf(t1, t2)); fv = fminf(fv, fmaxf(t1, t2));
    nv = fmaxf(nv, 0.01f);
    fv = fmaxf(fv, nv + 1e-6f);
    nearv = nv; farv = fv;
}

// ---------------- kernel 5a: init clip bounds ----------------
__global__ void init_minmax_kernel() {
    int i = threadIdx.x;
    if (i < Tdim) { g_lo[i] = 3.4e38f; g_hi[i] = 0.f; }
}

// ---------------- kernel 5b: global per-t min(starts)/max(starts) ----------------
// ref does jnp.clip(depth, starts.min(), starts.max()) with GLOBAL (all-ray) bounds.
__global__ void __launch_bounds__(256) minmax_kernel(const float* __restrict__ ro,
                                                     const float* __restrict__ rd) {
    __shared__ float slo[256], shi[256];
    int r = blockIdx.x * 256 + threadIdx.x;   // grid exactly covers Tdim*NRAYS
    int t = r / NRAYS;
    float ox = ro[r * 3 + 0], oy = ro[r * 3 + 1], oz = ro[r * 3 + 2];
    float dx = rd[r * 3 + 0], dy = rd[r * 3 + 1], dz = rd[r * 3 + 2];
    float nearv, farv;
    ray_near_far(ox, oy, oz, dx, dy, dz, nearv, farv);
    float step = (farv - nearv) * (1.f / 128.f);
    float hi = nearv + 127.f * step;
    slo[threadIdx.x] = nearv;
    shi[threadIdx.x] = hi;
    __syncthreads();
    for (int s = 128; s > 0; s >>= 1) {
        if (threadIdx.x < s) {
            slo[threadIdx.x] = fminf(slo[threadIdx.x], slo[threadIdx.x + s]);
            shi[threadIdx.x] = fmaxf(shi[threadIdx.x], shi[threadIdx.x + s]);
        }
        __syncthreads();
    }
    if (threadIdx.x == 0) {
        // all values positive -> int-bit compare is order-preserving; min/max are
        // order-independent -> deterministic.
        atomicMin((int*)&g_lo[t], __float_as_int(slo[0]));
        atomicMax((int*)&g_hi[t], __float_as_int(shi[0]));
    }
}

// ---------------- kernel 6: volume rendering ----------------
__global__ void __launch_bounds__(256) render_kernel(const float* __restrict__ ro,
                                                     const float* __restrict__ rd,
                                                     float* __restrict__ out) {
    int r = blockIdx.x * 256 + threadIdx.x;
    int t = r / NRAYS;
    float ox = ro[r * 3 + 0], oy = ro[r * 3 + 1], oz = ro[r * 3 + 2];
    float dx = rd[r * 3 + 0], dy = rd[r * 3 + 1], dz = rd[r * 3 + 2];
    float nearv, farv;
    ray_near_far(ox, oy, oz, dx, dy, dz, nearv, farv);
    float step = (farv - nearv) * (1.f / 128.f);

    const uint4* S8t = g_S8 + (size_t)t * VOXT;
    float Tr = 1.f, sw = 0.f, swd = 0.f;

#pragma unroll 4
    for (int k = 0; k < KSAMP; ++k) {
        float tm = nearv + ((float)k + 0.5f) * step;
        float px = ox + dx * tm;
        float py = oy + dy * tm;
        float pz = oz + dz * tm;
        float gx = fminf(fmaxf(px, 0.f), 1.f) * 95.f;
        float gy = fminf(fmaxf(py, 0.f), 1.f) * 95.f;
        float gz = fminf(fmaxf(pz, 0.f), 1.f) * 15.f;
        float fx0 = floorf(gx), fy0 = floorf(gy), fz0 = floorf(gz);
        int ix = (int)fx0, iy = (int)fy0, iz = (int)fz0;
        float fx = gx - fx0, fy = gy - fy0, fz = gz - fz0;

        uint4 u = __ldg(&S8t[(iz * Ydim + iy) * Xdim + ix]);
        float2 c00 = __half22float2(*reinterpret_cast<const __half2*>(&u.x)); // z0 y0
        float2 c01 = __half22float2(*reinterpret_cast<const __half2*>(&u.y)); // z0 y1
        float2 c10 = __half22float2(*reinterpret_cast<const __half2*>(&u.z)); // z1 y0
        float2 c11 = __half22float2(*reinterpret_cast<const __half2*>(&u.w)); // z1 y1

        float a0 = c00.x + fx * (c00.y - c00.x);
        float a1 = c01.x + fx * (c01.y - c01.x);
        float b0 = c10.x + fx * (c10.y - c10.x);
        float b1 = c11.x + fx * (c11.y - c11.x);
        float va = a0 + fy * (a1 - a0);
        float vb = b0 + fy * (b1 - b0);
        float s  = va + fz * (vb - va);

        // softplus (matches jax logaddexp(x,0) form)
        float dens = fmaxf(s, 0.f) + log1pf(__expf(-fabsf(s)));
        float dd = dens * step;
        float e = __expf(-dd);
        float w = Tr * (1.f - e);
        sw  += w;
        swd += w * (nearv + (float)k * step);
        Tr  *= e;
    }

    float depth = swd / (sw + 1e-10f);
    depth = fminf(fmaxf(depth, g_lo[t]), g_hi[t]);
    out[r] = depth;
}

// ---------------- launch ----------------
extern "C" void kernel_launch(void* const* d_in, const int* in_sizes, int n_in,
                              void* d_out, int out_size) {
    (void)in_sizes; (void)n_in; (void)out_size;
    const float* vol = (const float*)d_in[0];
    const float* ro  = (const float*)d_in[1];
    const float* rd  = (const float*)d_in[2];
    const float* cw  = (const float*)d_in[3];
    const float* cb  = (const float*)d_in[4];
    const float* dw  = (const float*)d_in[5];
    const float* db  = (const float*)d_in[6];
    float* out = (float*)d_out;

    cudaFuncSetAttribute(conv_kernel, cudaFuncAttributeMaxDynamicSharedMemorySize,
                         CONV_SMEM_BYTES);

    fold_kernel<<<(CIN * 27 * Zdim + 255) / 256, 256>>>(cw, cb, dw, db);

    dim3 cgrid(Xdim / TILE_X, Ydim / TILE_Y, Tdim * 8);  // (3, 6, 40) = 720 blocks
    dim3 cblk(16, 16);
    conv_kernel<<<cgrid, cblk, CONV_SMEM_BYTES>>>(vol);

    combine_kernel<<<(VOXALL + 255) / 256, 256>>>();
    expand_kernel<<<(VOXALL + 255) / 256, 256>>>();

    init_minmax_kernel<<<1, 32>>>();
    minmax_kernel<<<(Tdim * NRAYS) / 256, 256>>>(ro, rd);
    render_kernel<<<(Tdim * NRAYS) / 256, 256>>>(ro, rd, out);
}

// round 15
// speedup vs baseline: 1.0547x; 1.0039x over previous
#include <cuda_runtime.h>
#include <cuda_fp16.h>

// ---------------- problem constants ----------------
#define Fdim   8
#define Tdim   5
#define Zdim   16
#define Ydim   96
#define Xdim   96
#define NRAYS  32768
#define KSAMP  128
#define CIN    128               // Fdim*Zdim
#define VOXT   (Zdim*Ydim*Xdim)  // 147456 per t
#define VOXALL (Tdim*VOXT)       // 737280

// ---------------- scratch (device globals; no allocation) ----------------
__device__ float g_W2[CIN * 27 * Zdim];   // folded weights [ci][k][zo]
__device__ float g_bias2[Zdim];
__device__ float g_Spart[8][VOXALL];      // per-ci-chunk partial conv outputs
__device__ float g_S[VOXALL];             // combined density pre-activation volume
__device__ uint4 g_S8[VOXALL];            // 8 fp16 trilinear corners per cell
__device__ float g_lo[Tdim], g_hi[Tdim];  // global per-t clip bounds

// ---------------- f32x2 helpers ----------------
__device__ __forceinline__ unsigned long long pack2(float x) {
    unsigned long long r;
    unsigned u = __float_as_uint(x);
    asm("mov.b64 %0, {%1, %1};" : "=l"(r) : "r"(u));
    return r;
}
__device__ __forceinline__ void fma2(unsigned long long& c, unsigned long long a,
                                     unsigned long long b) {
    asm("fma.rn.f32x2 %0, %1, %2, %0;" : "+l"(c) : "l"(a), "l"(b));
}
__device__ __forceinline__ void unpack2(unsigned long long v, float& lo, float& hi) {
    unsigned ulo, uhi;
    asm("mov.b64 {%0, %1}, %2;" : "=r"(ulo), "=r"(uhi) : "l"(v));
    lo = __uint_as_float(ulo);
    hi = __uint_as_float(uhi);
}

// ---------------- kernel 1: fold dens_w into conv_w ----------------
// W2[zo][ci][k] folded: g_W2[(ci*27 + k)*16 + zo] = sum_f dens_w[f]*conv_w[f*16+zo][ci][k]
__global__ void fold_kernel(const float* __restrict__ cw, const float* __restrict__ cb,
                            const float* __restrict__ dw, const float* __restrict__ db) {
    int idx = blockIdx.x * blockDim.x + threadIdx.x;
    if (idx < CIN * 27 * Zdim) {
        int zo = idx & 15;
        int k  = (idx >> 4) % 27;
        int ci = idx / (27 * 16);
        float s = 0.f;
#pragma unroll
        for (int f = 0; f < Fdim; ++f)
            s += dw[f] * cw[(((f * Zdim + zo) * CIN) + ci) * 27 + k];
        g_W2[idx] = s;
    }
    if (idx < Zdim) {
        float s = db[0];
#pragma unroll
        for (int f = 0; f < Fdim; ++f) s += dw[f] * cb[f * Zdim + idx];
        g_bias2[idx] = s;
    }
}

// ---------------- kernel 2: folded 3D conv (128 in -> 16 out channels) ----------------
// Block: 32x16 output tile, one t, one 16-ci chunk. 256 threads, each 2 pixels x 16 zo.
#define TILE_X 32
#define TILE_Y 16
#define SIN_STRIDE 35
#define SIN_CI (3 * 18 * SIN_STRIDE)         // 1890 floats per ci
#define SIN_TOTAL (8 * SIN_CI)               // 15120
#define SW_TOTAL (8 * 27 * 16)               // 3456
#define CONV_SMEM_BYTES ((SIN_TOTAL + SW_TOTAL) * 4)

__global__ void __launch_bounds__(256) conv_kernel(const float* __restrict__ vol) {
    extern __shared__ float sm[];
    float* sIn = sm;
    float* sW  = sm + SIN_TOTAL;

    const int tx = threadIdx.x;   // 0..15
    const int ty = threadIdx.y;   // 0..15
    const int tid = ty * 16 + tx;
    const int x0 = blockIdx.x * TILE_X;
    const int y0 = blockIdx.y * TILE_Y;
    const int bz = blockIdx.z;
    const int t = bz >> 3;
    const int chunk = bz & 7;
    const int cibase = chunk * 16;

    unsigned long long accA[8], accB[8];
#pragma unroll
    for (int p = 0; p < 8; ++p) { accA[p] = 0ull; accB[p] = 0ull; }

    for (int s = 0; s < 2; ++s) {
        const int ci0 = cibase + s * 8;
        // cooperative input tile load: 8 ci x 3 t-planes x 18 x 34 (zero-padded)
        for (int e = tid; e < 8 * 3 * 18 * 34; e += 256) {
            int i  = e / (3 * 18 * 34);
            int r  = e % (3 * 18 * 34);
            int kd = r / (18 * 34);
            int r2 = r % (18 * 34);
            int yy = r2 / 34;
            int xx = r2 % 34;
            int ci = ci0 + i;
            int f = ci >> 4, z = ci & 15;
            int gt = t + kd - 1;
            int gy = y0 + yy - 1;
            int gx = x0 + xx - 1;
            float v = 0.f;
            if (gt >= 0 && gt < Tdim && gy >= 0 && gy < Ydim && gx >= 0 && gx < Xdim)
                v = vol[(((size_t)(f * Tdim + gt) * Zdim + z) * Ydim + gy) * Xdim + gx];
            sIn[((i * 3 + kd) * 18 + yy) * SIN_STRIDE + xx] = v;
        }
        // weights for this 8-ci sub-chunk (contiguous in g_W2)
        const float* W2g = g_W2 + (size_t)ci0 * 27 * 16;
        for (int e = tid; e < SW_TOTAL; e += 256) sW[e] = W2g[e];
        __syncthreads();

#pragma unroll 1
        for (int i = 0; i < 8; ++i) {
            const float* base_i = sIn + i * SIN_CI;
#pragma unroll
            for (int kd = 0; kd < 3; ++kd) {
#pragma unroll
                for (int kh = 0; kh < 3; ++kh) {
                    const float* row = base_i + (kd * 18 + ty + kh) * SIN_STRIDE + 2 * tx;
#pragma unroll
                    for (int kw = 0; kw < 3; ++kw) {
                        float a0 = row[kw];
                        float a1 = row[kw + 1];
                        unsigned long long ua0 = pack2(a0);
                        unsigned long long ua1 = pack2(a1);
                        const unsigned long long* wp =
                            (const unsigned long long*)(sW + (i * 27 + (kd * 9 + kh * 3 + kw)) * 16);
#pragma unroll
                        for (int p = 0; p < 8; ++p) {
                            unsigned long long w = wp[p];
                            fma2(accA[p], ua0, w);
                            fma2(accB[p], ua1, w);
                        }
                    }
                }
            }
        }
        __syncthreads();
    }

    // write partial sums
    float* outp = g_Spart[chunk];
    const int yy = y0 + ty;
    const int xA = x0 + 2 * tx;
#pragma unroll
    for (int p = 0; p < 8; ++p) {
        float a0, a1, b0, b1;
        unpack2(accA[p], a0, a1);  // (zo=2p, zo=2p+1) for pixel xA
        unpack2(accB[p], b0, b1);  // for pixel xA+1
        int zo = 2 * p;
        size_t o0 = (((size_t)t * Zdim + zo) * Ydim + yy) * Xdim + xA;
        size_t o1 = (((size_t)t * Zdim + zo + 1) * Ydim + yy) * Xdim + xA;
        outp[o0] = a0; outp[o0 + 1] = b0;
        outp[o1] = a1; outp[o1 + 1] = b1;
    }
}

// ---------------- kernel 3: combine partials + bias ----------------
__global__ void combine_kernel() {
    int idx = blockIdx.x * blockDim.x + threadIdx.x;
    if (idx >= VOXALL) return;
    int zo = (idx / (Ydim * Xdim)) % Zdim;
    float s = g_bias2[zo];
#pragma unroll
    for (int c = 0; c < 8; ++c) s += g_Spart[c][idx];
    g_S[idx] = s;
}

// ---------------- kernel 4: expand to 8-corner fp16 cells ----------------
__global__ void expand_kernel() {
    int idx = blockIdx.x * blockDim.x + threadIdx.x;
    if (idx >= VOXALL) return;
    int x = idx % Xdim;
    int y = (idx / Xdim) % Ydim;
    int z = (idx / (Xdim * Ydim)) % Zdim;
    int t = idx / (Xdim * Ydim * Zdim);
    int x1 = min(x + 1, Xdim - 1);
    int y1 = min(y + 1, Ydim - 1);
    int z1 = min(z + 1, Zdim - 1);
    const float* St = g_S + (size_t)t * VOXT;
#define AT(zz, yy, xx) St[((zz) * Ydim + (yy)) * Xdim + (xx)]
    __half2 h01 = __floats2half2_rn(AT(z,  y,  x), AT(z,  y,  x1));
    __half2 h23 = __floats2half2_rn(AT(z,  y1, x), AT(z,  y1, x1));
    __half2 h45 = __floats2half2_rn(AT(z1, y,  x), AT(z1, y,  x1));
    __half2 h67 = __floats2half2_rn(AT(z1, y1, x), AT(z1, y1, x1));
#undef AT
    uint4 u;
    u.x = *reinterpret_cast<unsigned*>(&h01);
    u.y = *reinterpret_cast<unsigned*>(&h23);
    u.z = *reinterpret_cast<unsigned*>(&h45);
    u.w = *reinterpret_cast<unsigned*>(&h67);
    g_S8[idx] = u;
}

// ---------------- ray box intersection (shared by minmax + render) ----------------
__device__ __forceinline__ void ray_near_far(float ox, float oy, float oz,
                                             float dx, float dy, float dz,
                                             float& nearv, float& farv) {
    float t1 = (0.f - ox) / dx, t2 = (1.f - ox) / dx;
    float nv = fminf(t1, t2), fv = fmaxf(t1, t2);
    t1 = (0.f - oy) / dy; t2 = (1.f - oy) / dy;
    nv = fmaxf(nv, fminf(t1, t2)); fv = fminf(fv, fmaxf(t1, t2));
    t1 = (0.f - oz) / dz; t2 = (1.f - oz) / dz;
    nv = fmaxf(nv, fminf(t1, t2)); fv = fminf(fv, fmaxf(t1, t2));
    nv = fmaxf(nv, 0.01f);
    fv = fmaxf(fv, nv + 1e-6f);
    nearv = nv; farv = fv;
}

// ---------------- kernel 5a: init clip bounds ----------------
__global__ void init_minmax_kernel() {
    int i = threadIdx.x;
    if (i < Tdim) { g_lo[i] = 3.4e38f; g_hi[i] = 0.f; }
}

// ---------------- kernel 5b: global per-t min(starts)/max(starts) ----------------
// ref does jnp.clip(depth, starts.min(), starts.max()) with GLOBAL (all-ray) bounds.
__global__ void __launch_bounds__(256) minmax_kernel(const float* __restrict__ ro,
                                                     const float* __restrict__ rd) {
    __shared__ float slo[256], shi[256];
    int r = blockIdx.x * 256 + threadIdx.x;   // grid exactly covers Tdim*NRAYS
    int t = r / NRAYS;
    float ox = ro[r * 3 + 0], oy = ro[r * 3 + 1], oz = ro[r * 3 + 2];
    float dx = rd[r * 3 + 0], dy = rd[r * 3 + 1], dz = rd[r * 3 + 2];
    float nearv, farv;
    ray_near_far(ox, oy, oz, dx, dy, dz, nearv, farv);
    float step = (farv - nearv) * (1.f / 128.f);
    float hi = nearv + 127.f * step;
    slo[threadIdx.x] = nearv;
    shi[threadIdx.x] = hi;
    __syncthreads();
    for (int s = 128; s > 0; s >>= 1) {
        if (threadIdx.x < s) {
            slo[threadIdx.x] = fminf(slo[threadIdx.x], slo[threadIdx.x + s]);
            shi[threadIdx.x] = fmaxf(shi[threadIdx.x], shi[threadIdx.x + s]);
        }
        __syncthreads();
    }
    if (threadIdx.x == 0) {
        // all values positive -> int-bit compare is order-preserving; min/max are
        // order-independent -> deterministic.
        atomicMin((int*)&g_lo[t], __float_as_int(slo[0]));
        atomicMax((int*)&g_hi[t], __float_as_int(shi[0]));
    }
}

// ---------------- kernel 6: volume rendering ----------------
__global__ void __launch_bounds__(256) render_kernel(const float* __restrict__ ro,
                                                     const float* __restrict__ rd,
                                                     float* __restrict__ out) {
    int r = blockIdx.x * 256 + threadIdx.x;
    int t = r / NRAYS;
    float ox = ro[r * 3 + 0], oy = ro[r * 3 + 1], oz = ro[r * 3 + 2];
    float dx = rd[r * 3 + 0], dy = rd[r * 3 + 1], dz = rd[r * 3 + 2];
    float nearv, farv;
    ray_near_far(ox, oy, oz, dx, dy, dz, nearv, farv);
    float step = (farv - nearv) * (1.f / 128.f);

    const uint4* S8t = g_S8 + (size_t)t * VOXT;
    float Tr = 1.f, sw = 0.f, swd = 0.f;

#pragma unroll 4
    for (int k = 0; k < KSAMP; ++k) {
        float tm = nearv + ((float)k + 0.5f) * step;
        float px = ox + dx * tm;
        float py = oy + dy * tm;
        float pz = oz + dz * tm;
        float gx = fminf(fmaxf(px, 0.f), 1.f) * 95.f;
        float gy = fminf(fmaxf(py, 0.f), 1.f) * 95.f;
        float gz = fminf(fmaxf(pz, 0.f), 1.f) * 15.f;
        float fx0 = floorf(gx), fy0 = floorf(gy), fz0 = floorf(gz);
        int ix = (int)fx0, iy = (int)fy0, iz = (int)fz0;
        float fx = gx - fx0, fy = gy - fy0, fz = gz - fz0;

        uint4 u = __ldg(&S8t[(iz * Ydim + iy) * Xdim + ix]);
        float2 c00 = __half22float2(*reinterpret_cast<const __half2*>(&u.x)); // z0 y0
        float2 c01 = __half22float2(*reinterpret_cast<const __half2*>(&u.y)); // z0 y1
        float2 c10 = __half22float2(*reinterpret_cast<const __half2*>(&u.z)); // z1 y0
        float2 c11 = __half22float2(*reinterpret_cast<const __half2*>(&u.w)); // z1 y1

        float a0 = c00.x + fx * (c00.y - c00.x);
        float a1 = c01.x + fx * (c01.y - c01.x);
        float b0 = c10.x + fx * (c10.y - c10.x);
        float b1 = c11.x + fx * (c11.y - c11.x);
        float va = a0 + fy * (a1 - a0);
        float vb = b0 + fy * (b1 - b0);
        float s  = va + fz * (vb - va);

        // softplus (matches jax logaddexp(x,0) form)
        float dens = fmaxf(s, 0.f) + log1pf(__expf(-fabsf(s)));
        float dd = dens * step;
        float e = __expf(-dd);
        float w = Tr * (1.f - e);
        sw  += w;
        swd += w * (nearv + (float)k * step);
        Tr  *= e;
    }

    float depth = swd / (sw + 1e-10f);
    depth = fminf(fmaxf(depth, g_lo[t]), g_hi[t]);
    out[r] = depth;
}

// ---------------- launch ----------------
extern "C" void kernel_launch(void* const* d_in, const int* in_sizes, int n_in,
                              void* d_out, int out_size) {
    (void)in_sizes; (void)n_in; (void)out_size;
    const float* vol = (const float*)d_in[0];
    const float* ro  = (const float*)d_in[1];
    const float* rd  = (const float*)d_in[2];
    const float* cw  = (const float*)d_in[3];
    const float* cb  = (const float*)d_in[4];
    const float* dw  = (const float*)d_in[5];
    const float* db  = (const float*)d_in[6];
    float* out = (float*)d_out;

    cudaFuncSetAttribute(conv_kernel, cudaFuncAttributeMaxDynamicSharedMemorySize,
                         CONV_SMEM_BYTES);

    fold_kernel<<<(CIN * 27 * Zdim + 255) / 256, 256>>>(cw, cb, dw, db);

    dim3 cgrid(Xdim / TILE_X, Ydim / TILE_Y, Tdim * 8);  // (3, 6, 40) = 720 blocks
    dim3 cblk(16, 16);
    conv_kernel<<<cgrid, cblk, CONV_SMEM_BYTES>>>(vol);

    combine_kernel<<<(VOXALL + 255) / 256, 256>>>();
    expand_kernel<<<(VOXALL + 255) / 256, 256>>>();

    init_minmax_kernel<<<1, 32>>>();
    minmax_kernel<<<(Tdim * NRAYS) / 256, 256>>>(ro, rd);
    render_kernel<<<(Tdim * NRAYS) / 256, 256>>>(ro, rd, out);
}

// round 16
// speedup vs baseline: 1.0558x; 1.0010x over previous
#include <cuda_runtime.h>
#include <cuda_fp16.h>

// ---------------- problem constants ----------------
#define Fdim   8
#define Tdim   5
#define Zdim   16
#define Ydim   96
#define Xdim   96
#define NRAYS  32768
#define KSAMP  128
#define CIN    128               // Fdim*Zdim
#define VOXT   (Zdim*Ydim*Xdim)  // 147456 per t
#define VOXALL (Tdim*VOXT)       // 737280

// ---------------- scratch (device globals; no allocation) ----------------
__device__ float g_W2[CIN * 27 * Zdim];   // folded weights [ci][k][zo]
__device__ float g_bias2[Zdim];
__device__ float g_Spart[8][VOXALL];      // per-ci-chunk partial conv outputs
__device__ float g_S[VOXALL];             // combined density pre-activation volume
__device__ uint4 g_S8[VOXALL];            // 8 fp16 trilinear corners per cell
__device__ float g_lo[Tdim], g_hi[Tdim];  // global per-t clip bounds

// ---------------- f32x2 helpers ----------------
__device__ __forceinline__ unsigned long long pack2(float x) {
    unsigned long long r;
    unsigned u = __float_as_uint(x);
    asm("mov.b64 %0, {%1, %1};" : "=l"(r) : "r"(u));
    return r;
}
__device__ __forceinline__ void fma2(unsigned long long& c, unsigned long long a,
                                     unsigned long long b) {
    asm("fma.rn.f32x2 %0, %1, %2, %0;" : "+l"(c) : "l"(a), "l"(b));
}
__device__ __forceinline__ void unpack2(unsigned long long v, float& lo, float& hi) {
    unsigned ulo, uhi;
    asm("mov.b64 {%0, %1}, %2;" : "=r"(ulo), "=r"(uhi) : "l"(v));
    lo = __uint_as_float(ulo);
    hi = __uint_as_float(uhi);
}

// ---------------- kernel 1: fold dens_w into conv_w ----------------
// W2[zo][ci][k] folded: g_W2[(ci*27 + k)*16 + zo] = sum_f dens_w[f]*conv_w[f*16+zo][ci][k]
__global__ void fold_kernel(const float* __restrict__ cw, const float* __restrict__ cb,
                            const float* __restrict__ dw, const float* __restrict__ db) {
    int idx = blockIdx.x * blockDim.x + threadIdx.x;
    if (idx < CIN * 27 * Zdim) {
        int zo = idx & 15;
        int k  = (idx >> 4) % 27;
        int ci = idx / (27 * 16);
        float s = 0.f;
#pragma unroll
        for (int f = 0; f < Fdim; ++f)
            s += dw[f] * cw[(((f * Zdim + zo) * CIN) + ci) * 27 + k];
        g_W2[idx] = s;
    }
    if (idx < Zdim) {
        float s = db[0];
#pragma unroll
        for (int f = 0; f < Fdim; ++f) s += dw[f] * cb[f * Zdim + idx];
        g_bias2[idx] = s;
    }
}

// ---------------- kernel 2: folded 3D conv (128 in -> 16 out channels) ----------------
// Block: 32x16 output tile, one t, one 16-ci chunk. 256 threads, each 2 pixels x 16 zo.
#define TILE_X 32
#define TILE_Y 16
#define SIN_STRIDE 35
#define SIN_CI (3 * 18 * SIN_STRIDE)         // 1890 floats per ci
#define SIN_TOTAL (8 * SIN_CI)               // 15120
#define SW_TOTAL (8 * 27 * 16)               // 3456
#define CONV_SMEM_BYTES ((SIN_TOTAL + SW_TOTAL) * 4)

__global__ void __launch_bounds__(256) conv_kernel(const float* __restrict__ vol) {
    extern __shared__ float sm[];
    float* sIn = sm;
    float* sW  = sm + SIN_TOTAL;

    const int tx = threadIdx.x;   // 0..15
    const int ty = threadIdx.y;   // 0..15
    const int tid = ty * 16 + tx;
    const int x0 = blockIdx.x * TILE_X;
    const int y0 = blockIdx.y * TILE_Y;
    const int bz = blockIdx.z;
    const int t = bz >> 3;
    const int chunk = bz & 7;
    const int cibase = chunk * 16;

    unsigned long long accA[8], accB[8];
#pragma unroll
    for (int p = 0; p < 8; ++p) { accA[p] = 0ull; accB[p] = 0ull; }

    for (int s = 0; s < 2; ++s) {
        const int ci0 = cibase + s * 8;
        // cooperative input tile load: 8 ci x 3 t-planes x 18 x 34 (zero-padded)
        for (int e = tid; e < 8 * 3 * 18 * 34; e += 256) {
            int i  = e / (3 * 18 * 34);
            int r  = e % (3 * 18 * 34);
            int kd = r / (18 * 34);
            int r2 = r % (18 * 34);
            int yy = r2 / 34;
            int xx = r2 % 34;
            int ci = ci0 + i;
            int f = ci >> 4, z = ci & 15;
            int gt = t + kd - 1;
            int gy = y0 + yy - 1;
            int gx = x0 + xx - 1;
            float v = 0.f;
            if (gt >= 0 && gt < Tdim && gy >= 0 && gy < Ydim && gx >= 0 && gx < Xdim)
                v = vol[(((size_t)(f * Tdim + gt) * Zdim + z) * Ydim + gy) * Xdim + gx];
            sIn[((i * 3 + kd) * 18 + yy) * SIN_STRIDE + xx] = v;
        }
        // weights for this 8-ci sub-chunk (contiguous in g_W2)
        const float* W2g = g_W2 + (size_t)ci0 * 27 * 16;
        for (int e = tid; e < SW_TOTAL; e += 256) sW[e] = W2g[e];
        __syncthreads();

#pragma unroll 1
        for (int i = 0; i < 8; ++i) {
            const float* base_i = sIn + i * SIN_CI;
#pragma unroll
            for (int kd = 0; kd < 3; ++kd) {
#pragma unroll
                for (int kh = 0; kh < 3; ++kh) {
                    const float* row = base_i + (kd * 18 + ty + kh) * SIN_STRIDE + 2 * tx;
#pragma unroll
                    for (int kw = 0; kw < 3; ++kw) {
                        float a0 = row[kw];
                        float a1 = row[kw + 1];
                        unsigned long long ua0 = pack2(a0);
                        unsigned long long ua1 = pack2(a1);
                        const unsigned long long* wp =
                            (const unsigned long long*)(sW + (i * 27 + (kd * 9 + kh * 3 + kw)) * 16);
#pragma unroll
                        for (int p = 0; p < 8; ++p) {
                            unsigned long long w = wp[p];
                            fma2(accA[p], ua0, w);
                            fma2(accB[p], ua1, w);
                        }
                    }
                }
            }
        }
        __syncthreads();
    }

    // write partial sums
    float* outp = g_Spart[chunk];
    const int yy = y0 + ty;
    const int xA = x0 + 2 * tx;
#pragma unroll
    for (int p = 0; p < 8; ++p) {
        float a0, a1, b0, b1;
        unpack2(accA[p], a0, a1);  // (zo=2p, zo=2p+1) for pixel xA
        unpack2(accB[p], b0, b1);  // for pixel xA+1
        int zo = 2 * p;
        size_t o0 = (((size_t)t * Zdim + zo) * Ydim + yy) * Xdim + xA;
        size_t o1 = (((size_t)t * Zdim + zo + 1) * Ydim + yy) * Xdim + xA;
        outp[o0] = a0; outp[o0 + 1] = b0;
        outp[o1] = a1; outp[o1 + 1] = b1;
    }
}

// ---------------- kernel 3: combine partials + bias ----------------
__global__ void combine_kernel() {
    int idx = blockIdx.x * blockDim.x + threadIdx.x;
    if (idx >= VOXALL) return;
    int zo = (idx / (Ydim * Xdim)) % Zdim;
    float s = g_bias2[zo];
#pragma unroll
    for (int c = 0; c < 8; ++c) s += g_Spart[c][idx];
    g_S[idx] = s;
}

// ---------------- kernel 4: expand to 8-corner fp16 cells ----------------
__global__ void expand_kernel() {
    int idx = blockIdx.x * blockDim.x + threadIdx.x;
    if (idx >= VOXALL) return;
    int x = idx % Xdim;
    int y = (idx / Xdim) % Ydim;
    int z = (idx / (Xdim * Ydim)) % Zdim;
    int t = idx / (Xdim * Ydim * Zdim);
    int x1 = min(x + 1, Xdim - 1);
    int y1 = min(y + 1, Ydim - 1);
    int z1 = min(z + 1, Zdim - 1);
    const float* St = g_S + (size_t)t * VOXT;
#define AT(zz, yy, xx) St[((zz) * Ydim + (yy)) * Xdim + (xx)]
    __half2 h01 = __floats2half2_rn(AT(z,  y,  x), AT(z,  y,  x1));
    __half2 h23 = __floats2half2_rn(AT(z,  y1, x), AT(z,  y1, x1));
    __half2 h45 = __floats2half2_rn(AT(z1, y,  x), AT(z1, y,  x1));
    __half2 h67 = __floats2half2_rn(AT(z1, y1, x), AT(z1, y1, x1));
#undef AT
    uint4 u;
    u.x = *reinterpret_cast<unsigned*>(&h01);
    u.y = *reinterpret_cast<unsigned*>(&h23);
    u.z = *reinterpret_cast<unsigned*>(&h45);
    u.w = *reinterpret_cast<unsigned*>(&h67);
    g_S8[idx] = u;
}

// ---------------- ray box intersection (shared by minmax + render) ----------------
__device__ __forceinline__ void ray_near_far(float ox, float oy, float oz,
                                             float dx, float dy, float dz,
                                             float& nearv, float& farv) {
    float t1 = (0.f - ox) / dx, t2 = (1.f - ox) / dx;
    float nv = fminf(t1, t2), fv = fmaxf(t1, t2);
    t1 = (0.f - oy) / dy; t2 = (1.f - oy) / dy;
    nv = fmaxf(nv, fminf(t1, t2)); fv = fminf(fv, fmaxf(t1, t2));
    t1 = (0.f - oz) / dz; t2 = (1.f - oz) / dz;
    nv = fmaxf(nv, fminf(t1, t2)); fv = fminf(fv, fmaxf(t1, t2));
    nv = fmaxf(nv, 0.01f);
    fv = fmaxf(fv, nv + 1e-6f);
    nearv = nv; farv = fv;
}

// ---------------- kernel 5a: init clip bounds ----------------
__global__ void init_minmax_kernel() {
    int i = threadIdx.x;
    if (i < Tdim) { g_lo[i] = 3.4e38f; g_hi[i] = 0.f; }
}

// ---------------- kernel 5b: global per-t min(starts)/max(starts) ----------------
// ref does jnp.clip(depth, starts.min(), starts.max()) with GLOBAL (all-ray) bounds.
__global__ void __launch_bounds__(256) minmax_kernel(const float* __restrict__ ro,
                                                     const float* __restrict__ rd) {
    __shared__ float slo[256], shi[256];
    int r = blockIdx.x * 256 + threadIdx.x;   // grid exactly covers Tdim*NRAYS
    int t = r / NRAYS;
    float ox = ro[r * 3 + 0], oy = ro[r * 3 + 1], oz = ro[r * 3 + 2];
    float dx = rd[r * 3 + 0], dy = rd[r * 3 + 1], dz = rd[r * 3 + 2];
    float nearv, farv;
    ray_near_far(ox, oy, oz, dx, dy, dz, nearv, farv);
    float step = (farv - nearv) * (1.f / 128.f);
    float hi = nearv + 127.f * step;
    slo[threadIdx.x] = nearv;
    shi[threadIdx.x] = hi;
    __syncthreads();
    for (int s = 128; s > 0; s >>= 1) {
        if (threadIdx.x < s) {
            slo[threadIdx.x] = fminf(slo[threadIdx.x], slo[threadIdx.x + s]);
            shi[threadIdx.x] = fmaxf(shi[threadIdx.x], shi[threadIdx.x + s]);
        }
        __syncthreads();
    }
    if (threadIdx.x == 0) {
        // all values positive -> int-bit compare is order-preserving; min/max are
        // order-independent -> deterministic.
        atomicMin((int*)&g_lo[t], __float_as_int(slo[0]));
        atomicMax((int*)&g_hi[t], __float_as_int(shi[0]));
    }
}

// ---------------- kernel 6: volume rendering ----------------
__global__ void __launch_bounds__(256) render_kernel(const float* __restrict__ ro,
                                                     const float* __restrict__ rd,
                                                     float* __restrict__ out) {
    int r = blockIdx.x * 256 + threadIdx.x;
    int t = r / NRAYS;
    float ox = ro[r * 3 + 0], oy = ro[r * 3 + 1], oz = ro[r * 3 + 2];
    float dx = rd[r * 3 + 0], dy = rd[r * 3 + 1], dz = rd[r * 3 + 2];
    float nearv, farv;
    ray_near_far(ox, oy, oz, dx, dy, dz, nearv, farv);
    float step = (farv - nearv) * (1.f / 128.f);

    const uint4* S8t = g_S8 + (size_t)t * VOXT;
    float Tr = 1.f, sw = 0.f, swd = 0.f;

#pragma unroll 4
    for (int k = 0; k < KSAMP; ++k) {
        float tm = nearv + ((float)k + 0.5f) * step;
        float px = ox + dx * tm;
        float py = oy + dy * tm;
        float pz = oz + dz * tm;
        float gx = fminf(fmaxf(px, 0.f), 1.f) * 95.f;
        float gy = fminf(fmaxf(py, 0.f), 1.f) * 95.f;
        float gz = fminf(fmaxf(pz, 0.f), 1.f) * 15.f;
        float fx0 = floorf(gx), fy0 = floorf(gy), fz0 = floorf(gz);
        int ix = (int)fx0, iy = (int)fy0, iz = (int)fz0;
        float fx = gx - fx0, fy = gy - fy0, fz = gz - fz0;

        uint4 u = __ldg(&S8t[(iz * Ydim + iy) * Xdim + ix]);
        float2 c00 = __half22float2(*reinterpret_cast<const __half2*>(&u.x)); // z0 y0
        float2 c01 = __half22float2(*reinterpret_cast<const __half2*>(&u.y)); // z0 y1
        float2 c10 = __half22float2(*reinterpret_cast<const __half2*>(&u.z)); // z1 y0
        float2 c11 = __half22float2(*reinterpret_cast<const __half2*>(&u.w)); // z1 y1

        float a0 = c00.x + fx * (c00.y - c00.x);
        float a1 = c01.x + fx * (c01.y - c01.x);
        float b0 = c10.x + fx * (c10.y - c10.x);
        float b1 = c11.x + fx * (c11.y - c11.x);
        float va = a0 + fy * (a1 - a0);
        float vb = b0 + fy * (b1 - b0);
        float s  = va + fz * (vb - va);

        // softplus (matches jax logaddexp(x,0) form)
        float dens = fmaxf(s, 0.f) + log1pf(__expf(-fabsf(s)));
        float dd = dens * step;
        float e = __expf(-dd);
        float w = Tr * (1.f - e);
        sw  += w;
        swd += w * (nearv + (float)k * step);
        Tr  *= e;
    }

    float depth = swd / (sw + 1e-10f);
    depth = fminf(fmaxf(depth, g_lo[t]), g_hi[t]);
    out[r] = depth;
}

// ---------------- launch ----------------
extern "C" void kernel_launch(void* const* d_in, const int* in_sizes, int n_in,
                              void* d_out, int out_size) {
    (void)in_sizes; (void)n_in; (void)out_size;
    const float* vol = (const float*)d_in[0];
    const float* ro  = (const float*)d_in[1];
    const float* rd  = (const float*)d_in[2];
    const float* cw  = (const float*)d_in[3];
    const float* cb  = (const float*)d_in[4];
    const float* dw  = (const float*)d_in[5];
    const float* db  = (const float*)d_in[6];
    float* out = (float*)d_out;

    cudaFuncSetAttribute(conv_kernel, cudaFuncAttributeMaxDynamicSharedMemorySize,
                         CONV_SMEM_BYTES);

    fold_kernel<<<(CIN * 27 * Zdim + 255) / 256, 256>>>(cw, cb, dw, db);

    dim3 cgrid(Xdim / TILE_X, Ydim / TILE_Y, Tdim * 8);  // (3, 6, 40) = 720 blocks
    dim3 cblk(16, 16);
    conv_kernel<<<cgrid, cblk, CONV_SMEM_BYTES>>>(vol);

    combine_kernel<<<(VOXALL + 255) / 256, 256>>>();
    expand_kernel<<<(VOXALL + 255) / 256, 256>>>();

    init_minmax_kernel<<<1, 32>>>();
    minmax_kernel<<<(Tdim * NRAYS) / 256, 256>>>(ro, rd);
    render_kernel<<<(Tdim * NRAYS) / 256, 256>>>(ro, rd, out);
}